// round 6
// baseline (speedup 1.0000x reference)
#include <cuda_runtime.h>
#include <math.h>

// Problem dims (fixed by reference setup_inputs)
#define BB 64
#define FF 128
#define TT 4096
#define KK 13
#define NN (BB*TT)   // 262144 samples per coefficient

// ---- device scratch (static: no allocation allowed) ----
__device__ float  g_basis[KK][FF];
__device__ float  g_cT[KK * NN];       // cepstra, layout [k][b*T+t]
__device__ float  g_cP[KK * NN];
__device__ double g_sum[2][KK];
__device__ double g_sumsq[2][KK];
__device__ float  g_mean[2][KK];
__device__ float  g_rstd[2][KK];
__device__ double g_mcd_acc;

// ---------------------------------------------------------------------------
// K0: zero accumulators, build orthonormal DCT-II basis on device
// ---------------------------------------------------------------------------
__global__ void k0_init() {
    int i = threadIdx.x;
    if (i < KK) {
        g_sum[0][i] = 0.0; g_sum[1][i] = 0.0;
        g_sumsq[0][i] = 0.0; g_sumsq[1][i] = 0.0;
    }
    if (i == 0) g_mcd_acc = 0.0;
    for (int idx = i; idx < KK * FF; idx += blockDim.x) {
        int k = idx / FF, f = idx % FF;
        float scale = (k == 0) ? sqrtf(1.0f / FF) : sqrtf(2.0f / FF);
        g_basis[k][f] = cospif((f + 0.5f) * (float)k / (float)FF) * scale;
    }
}

// ---------------------------------------------------------------------------
// K1: x -> log1p(|x|) -> 13-pt DCT for both tensors. Writes cepstra [k][n].
// One thread handles 2 adjacent t values (float2 coalesced loads/stores).
// Grid: (TT/512, BB), 256 threads.
// ---------------------------------------------------------------------------
__global__ __launch_bounds__(256) void k1_dct(const float* __restrict__ xt,
                                              const float* __restrict__ xp) {
    __shared__ float sb[KK][FF];
    for (int i = threadIdx.x; i < KK * FF; i += blockDim.x)
        ((float*)sb)[i] = ((const float*)g_basis)[i];
    __syncthreads();

    const int b  = blockIdx.y;
    const int t2 = blockIdx.x * blockDim.x + threadIdx.x;   // float2 index along T
    const float2* pt = (const float2*)(xt + (size_t)b * FF * TT);
    const float2* pp = (const float2*)(xp + (size_t)b * FF * TT);

    float aTx[KK], aTy[KK], aPx[KK], aPy[KK];
#pragma unroll
    for (int k = 0; k < KK; k++) { aTx[k]=0.f; aTy[k]=0.f; aPx[k]=0.f; aPy[k]=0.f; }

#pragma unroll 2
    for (int f = 0; f < FF; f++) {
        float2 vt = pt[f * (TT/2) + t2];
        float2 vp = pp[f * (TT/2) + t2];
        float ltx = __logf(1.0f + fabsf(vt.x));
        float lty = __logf(1.0f + fabsf(vt.y));
        float lpx = __logf(1.0f + fabsf(vp.x));
        float lpy = __logf(1.0f + fabsf(vp.y));
#pragma unroll
        for (int k = 0; k < KK; k++) {
            float w = sb[k][f];
            aTx[k] = fmaf(w, ltx, aTx[k]);
            aTy[k] = fmaf(w, lty, aTy[k]);
            aPx[k] = fmaf(w, lpx, aPx[k]);
            aPy[k] = fmaf(w, lpy, aPy[k]);
        }
    }

    const int n2 = b * (TT/2) + t2;   // float2 index into [k][NN]
#pragma unroll
    for (int k = 0; k < KK; k++) {
        ((float2*)(g_cT + (size_t)k * NN))[n2] = make_float2(aTx[k], aTy[k]);
        ((float2*)(g_cP + (size_t)k * NN))[n2] = make_float2(aPx[k], aPy[k]);
    }
}

// ---------------------------------------------------------------------------
// K2: per-coefficient sum / sumsq for both tensors.
// Grid-stride over NN; warp reduce -> shared accum -> 1 global atomic/block/qty.
// ---------------------------------------------------------------------------
__global__ __launch_bounds__(256) void k2_stats() {
    float s[2][KK], ss[2][KK];
#pragma unroll
    for (int t = 0; t < 2; t++)
#pragma unroll
        for (int k = 0; k < KK; k++) { s[t][k] = 0.f; ss[t][k] = 0.f; }

    for (int n = blockIdx.x * blockDim.x + threadIdx.x; n < NN;
         n += gridDim.x * blockDim.x) {
#pragma unroll
        for (int k = 0; k < KK; k++) {
            float a = g_cT[(size_t)k * NN + n];
            float c = g_cP[(size_t)k * NN + n];
            s[0][k] += a; ss[0][k] = fmaf(a, a, ss[0][k]);
            s[1][k] += c; ss[1][k] = fmaf(c, c, ss[1][k]);
        }
    }

    __shared__ float sh_s[2][KK], sh_ss[2][KK];
    if (threadIdx.x < 2 * KK) {
        ((float*)sh_s)[threadIdx.x] = 0.f;
        ((float*)sh_ss)[threadIdx.x] = 0.f;
    }
    __syncthreads();

#pragma unroll
    for (int t = 0; t < 2; t++)
#pragma unroll
        for (int k = 0; k < KK; k++) {
            float v1 = s[t][k], v2 = ss[t][k];
            for (int o = 16; o > 0; o >>= 1) {
                v1 += __shfl_down_sync(0xffffffffu, v1, o);
                v2 += __shfl_down_sync(0xffffffffu, v2, o);
            }
            if ((threadIdx.x & 31) == 0) {
                atomicAdd(&sh_s[t][k], v1);
                atomicAdd(&sh_ss[t][k], v2);
            }
        }
    __syncthreads();
    if (threadIdx.x < 2 * KK) {
        int t = threadIdx.x / KK, k = threadIdx.x % KK;
        atomicAdd(&g_sum[t][k],   (double)sh_s[t][k]);
        atomicAdd(&g_sumsq[t][k], (double)sh_ss[t][k]);
    }
}

// ---------------------------------------------------------------------------
// K2b: finalize mean / 1/(std+1e-6)   (ddof=1, matches torch/jnp std)
// ---------------------------------------------------------------------------
__global__ void k2b_finalize() {
    int i = threadIdx.x;
    if (i < 2 * KK) {
        int t = i / KK, k = i % KK;
        double s  = g_sum[t][k];
        double mean = s / (double)NN;
        double var  = (g_sumsq[t][k] - s * s / (double)NN) / (double)(NN - 1);
        if (var < 0.0) var = 0.0;
        g_mean[t][k] = (float)mean;
        g_rstd[t][k] = (float)(1.0 / (sqrt(var) + 1e-6));
    }
}

// ---------------------------------------------------------------------------
// K3: mcd sum over all (b,t). d_k = cT'*rT - cP'*rP; mcd = sqrt(2*sum d^2)
// (the 10/ln10 scale and /N are applied in K4)
// ---------------------------------------------------------------------------
__global__ __launch_bounds__(256) void k3_mcd() {
    __shared__ float srT[KK], srP[KK], soff[KK];
    if (threadIdx.x < KK) {
        int k = threadIdx.x;
        float rT = g_rstd[0][k], rP = g_rstd[1][k];
        srT[k] = rT; srP[k] = rP;
        soff[k] = g_mean[0][k] * rT - g_mean[1][k] * rP;
    }
    __syncthreads();

    float acc = 0.f;
    for (int n = blockIdx.x * blockDim.x + threadIdx.x; n < NN;
         n += gridDim.x * blockDim.x) {
        float sum = 0.f;
#pragma unroll
        for (int k = 0; k < KK; k++) {
            float d = g_cT[(size_t)k * NN + n] * srT[k]
                    - g_cP[(size_t)k * NN + n] * srP[k]
                    - soff[k];
            sum = fmaf(d, d, sum);
        }
        acc += sqrtf(2.0f * sum);
    }

    __shared__ float sh_acc;
    if (threadIdx.x == 0) sh_acc = 0.f;
    __syncthreads();
    for (int o = 16; o > 0; o >>= 1) acc += __shfl_down_sync(0xffffffffu, acc, o);
    if ((threadIdx.x & 31) == 0) atomicAdd(&sh_acc, acc);
    __syncthreads();
    if (threadIdx.x == 0) atomicAdd(&g_mcd_acc, (double)sh_acc);
}

// ---------------------------------------------------------------------------
// K4: final scalar
// ---------------------------------------------------------------------------
__global__ void k4_final(float* out) {
    // 10 / ln(10)
    out[0] = (float)(g_mcd_acc * 4.342944819032518 / (double)NN);
}

extern "C" void kernel_launch(void* const* d_in, const int* in_sizes, int n_in,
                              void* d_out, int out_size) {
    const float* mel_true = (const float*)d_in[0];
    const float* mel_pred = (const float*)d_in[1];
    float* out = (float*)d_out;

    k0_init<<<1, 256>>>();

    dim3 g1(TT / 512, BB);           // 8 x 64 = 512 blocks, 2 t per thread
    k1_dct<<<g1, 256>>>(mel_true, mel_pred);

    k2_stats<<<512, 256>>>();
    k2b_finalize<<<1, 32>>>();
    k3_mcd<<<512, 256>>>();
    k4_final<<<1, 1>>>(out);
}

// round 7
// speedup vs baseline: 1.0033x; 1.0033x over previous
#include <cuda_runtime.h>
#include <math.h>

// Problem dims (fixed by reference setup_inputs)
#define BB 64
#define FF 128
#define TT 4096
#define KK 13
#define NN (BB*TT)   // 262144 samples per coefficient

// ---- device scratch (static: no allocation allowed) ----
__device__ float  g_basis[KK][FF];
__device__ float  g_cT[KK * NN];       // cepstra, layout [k][b*T+t]
__device__ float  g_cP[KK * NN];
__device__ double g_sum[2][KK];
__device__ double g_sumsq[2][KK];
__device__ float  g_mean[2][KK];
__device__ float  g_rstd[2][KK];
__device__ double g_mcd_acc;

// ---------------------------------------------------------------------------
// K0: zero accumulators, build orthonormal DCT-II basis on device
// ---------------------------------------------------------------------------
__global__ void k0_init() {
    int i = threadIdx.x;
    if (i < KK) {
        g_sum[0][i] = 0.0; g_sum[1][i] = 0.0;
        g_sumsq[0][i] = 0.0; g_sumsq[1][i] = 0.0;
    }
    if (i == 0) g_mcd_acc = 0.0;
    for (int idx = i; idx < KK * FF; idx += blockDim.x) {
        int k = idx / FF, f = idx % FF;
        float scale = (k == 0) ? sqrtf(1.0f / FF) : sqrtf(2.0f / FF);
        g_basis[k][f] = cospif((f + 0.5f) * (float)k / (float)FF) * scale;
    }
}

// ---------------------------------------------------------------------------
// K1: x -> log1p(|x|) -> 13-pt DCT for both tensors. Writes cepstra [k][n].
// One thread handles 2 adjacent t values (float2 coalesced loads/stores).
// Grid: (TT/512, BB), 256 threads.
// ---------------------------------------------------------------------------
__global__ __launch_bounds__(256) void k1_dct(const float* __restrict__ xt,
                                              const float* __restrict__ xp) {
    __shared__ float sb[KK][FF];
    for (int i = threadIdx.x; i < KK * FF; i += blockDim.x)
        ((float*)sb)[i] = ((const float*)g_basis)[i];
    __syncthreads();

    const int b  = blockIdx.y;
    const int t2 = blockIdx.x * blockDim.x + threadIdx.x;   // float2 index along T
    const float2* pt = (const float2*)(xt + (size_t)b * FF * TT);
    const float2* pp = (const float2*)(xp + (size_t)b * FF * TT);

    float aTx[KK], aTy[KK], aPx[KK], aPy[KK];
#pragma unroll
    for (int k = 0; k < KK; k++) { aTx[k]=0.f; aTy[k]=0.f; aPx[k]=0.f; aPy[k]=0.f; }

#pragma unroll 2
    for (int f = 0; f < FF; f++) {
        float2 vt = pt[f * (TT/2) + t2];
        float2 vp = pp[f * (TT/2) + t2];
        float ltx = __logf(1.0f + fabsf(vt.x));
        float lty = __logf(1.0f + fabsf(vt.y));
        float lpx = __logf(1.0f + fabsf(vp.x));
        float lpy = __logf(1.0f + fabsf(vp.y));
#pragma unroll
        for (int k = 0; k < KK; k++) {
            float w = sb[k][f];
            aTx[k] = fmaf(w, ltx, aTx[k]);
            aTy[k] = fmaf(w, lty, aTy[k]);
            aPx[k] = fmaf(w, lpx, aPx[k]);
            aPy[k] = fmaf(w, lpy, aPy[k]);
        }
    }

    const int n2 = b * (TT/2) + t2;   // float2 index into [k][NN]
#pragma unroll
    for (int k = 0; k < KK; k++) {
        ((float2*)(g_cT + (size_t)k * NN))[n2] = make_float2(aTx[k], aTy[k]);
        ((float2*)(g_cP + (size_t)k * NN))[n2] = make_float2(aPx[k], aPy[k]);
    }
}

// ---------------------------------------------------------------------------
// K2: per-coefficient sum / sumsq for both tensors.
// Grid-stride over NN; warp reduce -> shared accum -> 1 global atomic/block/qty.
// ---------------------------------------------------------------------------
__global__ __launch_bounds__(256) void k2_stats() {
    float s[2][KK], ss[2][KK];
#pragma unroll
    for (int t = 0; t < 2; t++)
#pragma unroll
        for (int k = 0; k < KK; k++) { s[t][k] = 0.f; ss[t][k] = 0.f; }

    for (int n = blockIdx.x * blockDim.x + threadIdx.x; n < NN;
         n += gridDim.x * blockDim.x) {
#pragma unroll
        for (int k = 0; k < KK; k++) {
            float a = g_cT[(size_t)k * NN + n];
            float c = g_cP[(size_t)k * NN + n];
            s[0][k] += a; ss[0][k] = fmaf(a, a, ss[0][k]);
            s[1][k] += c; ss[1][k] = fmaf(c, c, ss[1][k]);
        }
    }

    __shared__ float sh_s[2][KK], sh_ss[2][KK];
    if (threadIdx.x < 2 * KK) {
        ((float*)sh_s)[threadIdx.x] = 0.f;
        ((float*)sh_ss)[threadIdx.x] = 0.f;
    }
    __syncthreads();

#pragma unroll
    for (int t = 0; t < 2; t++)
#pragma unroll
        for (int k = 0; k < KK; k++) {
            float v1 = s[t][k], v2 = ss[t][k];
            for (int o = 16; o > 0; o >>= 1) {
                v1 += __shfl_down_sync(0xffffffffu, v1, o);
                v2 += __shfl_down_sync(0xffffffffu, v2, o);
            }
            if ((threadIdx.x & 31) == 0) {
                atomicAdd(&sh_s[t][k], v1);
                atomicAdd(&sh_ss[t][k], v2);
            }
        }
    __syncthreads();
    if (threadIdx.x < 2 * KK) {
        int t = threadIdx.x / KK, k = threadIdx.x % KK;
        atomicAdd(&g_sum[t][k],   (double)sh_s[t][k]);
        atomicAdd(&g_sumsq[t][k], (double)sh_ss[t][k]);
    }
}

// ---------------------------------------------------------------------------
// K2b: finalize mean / 1/(std+1e-6)   (ddof=1, matches torch/jnp std)
// ---------------------------------------------------------------------------
__global__ void k2b_finalize() {
    int i = threadIdx.x;
    if (i < 2 * KK) {
        int t = i / KK, k = i % KK;
        double s  = g_sum[t][k];
        double mean = s / (double)NN;
        double var  = (g_sumsq[t][k] - s * s / (double)NN) / (double)(NN - 1);
        if (var < 0.0) var = 0.0;
        g_mean[t][k] = (float)mean;
        g_rstd[t][k] = (float)(1.0 / (sqrt(var) + 1e-6));
    }
}

// ---------------------------------------------------------------------------
// K3: mcd sum over all (b,t). d_k = cT'*rT - cP'*rP; mcd = sqrt(2*sum d^2)
// (the 10/ln10 scale and /N are applied in K4)
// ---------------------------------------------------------------------------
__global__ __launch_bounds__(256) void k3_mcd() {
    __shared__ float srT[KK], srP[KK], soff[KK];
    if (threadIdx.x < KK) {
        int k = threadIdx.x;
        float rT = g_rstd[0][k], rP = g_rstd[1][k];
        srT[k] = rT; srP[k] = rP;
        soff[k] = g_mean[0][k] * rT - g_mean[1][k] * rP;
    }
    __syncthreads();

    float acc = 0.f;
    for (int n = blockIdx.x * blockDim.x + threadIdx.x; n < NN;
         n += gridDim.x * blockDim.x) {
        float sum = 0.f;
#pragma unroll
        for (int k = 0; k < KK; k++) {
            float d = g_cT[(size_t)k * NN + n] * srT[k]
                    - g_cP[(size_t)k * NN + n] * srP[k]
                    - soff[k];
            sum = fmaf(d, d, sum);
        }
        acc += sqrtf(2.0f * sum);
    }

    __shared__ float sh_acc;
    if (threadIdx.x == 0) sh_acc = 0.f;
    __syncthreads();
    for (int o = 16; o > 0; o >>= 1) acc += __shfl_down_sync(0xffffffffu, acc, o);
    if ((threadIdx.x & 31) == 0) atomicAdd(&sh_acc, acc);
    __syncthreads();
    if (threadIdx.x == 0) atomicAdd(&g_mcd_acc, (double)sh_acc);
}

// ---------------------------------------------------------------------------
// K4: final scalar
// ---------------------------------------------------------------------------
__global__ void k4_final(float* out) {
    // 10 / ln(10)
    out[0] = (float)(g_mcd_acc * 4.342944819032518 / (double)NN);
}

extern "C" void kernel_launch(void* const* d_in, const int* in_sizes, int n_in,
                              void* d_out, int out_size) {
    const float* mel_true = (const float*)d_in[0];
    const float* mel_pred = (const float*)d_in[1];
    float* out = (float*)d_out;

    k0_init<<<1, 256>>>();

    dim3 g1(TT / 512, BB);           // 8 x 64 = 512 blocks, 2 t per thread
    k1_dct<<<g1, 256>>>(mel_true, mel_pred);

    k2_stats<<<512, 256>>>();
    k2b_finalize<<<1, 32>>>();
    k3_mcd<<<512, 256>>>();
    k4_final<<<1, 1>>>(out);
}

// round 8
// speedup vs baseline: 1.0473x; 1.0438x over previous
#include <cuda_runtime.h>
#include <cuda_fp16.h>
#include <math.h>

// Problem dims (fixed by reference setup_inputs)
#define BB 64
#define FF 128
#define TT 4096
#define KK 13
#define NN (BB*TT)   // 262144 samples per coefficient
#define T2 (TT/2)

// ---- device scratch (static: no allocation allowed) ----
__device__ float    g_basis[KK][FF/2];   // folded basis, pre-scaled by ln(2)*dct_scale
__device__ __half   g_cT16[(size_t)KK * NN];   // cepstra fp16, layout [k][b*T+t]
__device__ __half   g_cP16[(size_t)KK * NN];
__device__ double   g_sum[2][KK];
__device__ double   g_sumsq[2][KK];
__device__ double   g_mcd_acc;
__device__ unsigned g_count;

// ---------------------------------------------------------------------------
// K0: zero accumulators, build folded+scaled DCT basis.
// basis[k][f] (f<64) multiplies (x[f] + (-1)^k x[127-f]); ln2 folded in so the
// elementwise op is just log2(1+|x|)  (FADD + MUFU.LG2, no FMUL).
// ---------------------------------------------------------------------------
__global__ void k0_init() {
    int i = threadIdx.x;
    if (i < KK) {
        g_sum[0][i] = 0.0; g_sum[1][i] = 0.0;
        g_sumsq[0][i] = 0.0; g_sumsq[1][i] = 0.0;
    }
    if (i == 0) { g_mcd_acc = 0.0; g_count = 0u; }
    const float LN2 = 0.6931471805599453f;
    for (int idx = i; idx < KK * (FF/2); idx += blockDim.x) {
        int k = idx / (FF/2), f = idx % (FF/2);
        float scale = (k == 0) ? sqrtf(1.0f / FF) : sqrtf(2.0f / FF);
        // argument (2f+1)*k/256 is exact in fp32 (numerator <= 1524)
        g_basis[k][f] = cospif((float)((2*f + 1) * k) * (1.0f/256.0f)) * scale * LN2;
    }
}

// ---------------------------------------------------------------------------
// K1: log2(1+|x|) -> folded 13-pt DCT for both tensors, fp16 cepstra out,
// fused per-coefficient sum/sumsq (warp shuffle -> shared -> double atomics).
// One thread handles 2 adjacent t values (float2/half2). Grid: (8, 64) x 256.
// ---------------------------------------------------------------------------
__global__ __launch_bounds__(256) void k1_dct(const float* __restrict__ xt,
                                              const float* __restrict__ xp) {
    __shared__ float sb[KK][FF/2];
    for (int i = threadIdx.x; i < KK * (FF/2); i += blockDim.x)
        ((float*)sb)[i] = ((const float*)g_basis)[i];
    __syncthreads();

    const int b  = blockIdx.y;
    const int t2 = blockIdx.x * blockDim.x + threadIdx.x;   // float2 index along T
    const float2* pt = (const float2*)(xt + (size_t)b * FF * TT) + t2;
    const float2* pp = (const float2*)(xp + (size_t)b * FF * TT) + t2;

    float aTx[KK], aTy[KK], aPx[KK], aPy[KK];
#pragma unroll
    for (int k = 0; k < KK; k++) { aTx[k]=0.f; aTy[k]=0.f; aPx[k]=0.f; aPy[k]=0.f; }

#pragma unroll 2
    for (int f = 0; f < FF/2; f++) {
        float2 tl = pt[(size_t)f * T2];
        float2 th = pt[(size_t)(FF-1-f) * T2];
        float2 pl = pp[(size_t)f * T2];
        float2 ph = pp[(size_t)(FF-1-f) * T2];

        float ltlx = __log2f(1.0f + fabsf(tl.x));
        float ltly = __log2f(1.0f + fabsf(tl.y));
        float lthx = __log2f(1.0f + fabsf(th.x));
        float lthy = __log2f(1.0f + fabsf(th.y));
        float lplx = __log2f(1.0f + fabsf(pl.x));
        float lply = __log2f(1.0f + fabsf(pl.y));
        float lphx = __log2f(1.0f + fabsf(ph.x));
        float lphy = __log2f(1.0f + fabsf(ph.y));

        float sTx = ltlx + lthx, dTx = ltlx - lthx;
        float sTy = ltly + lthy, dTy = ltly - lthy;
        float sPx = lplx + lphx, dPx = lplx - lphx;
        float sPy = lply + lphy, dPy = lply - lphy;

#pragma unroll
        for (int k = 0; k < KK; k++) {
            float w = sb[k][f];
            if ((k & 1) == 0) {
                aTx[k] = fmaf(w, sTx, aTx[k]);
                aTy[k] = fmaf(w, sTy, aTy[k]);
                aPx[k] = fmaf(w, sPx, aPx[k]);
                aPy[k] = fmaf(w, sPy, aPy[k]);
            } else {
                aTx[k] = fmaf(w, dTx, aTx[k]);
                aTy[k] = fmaf(w, dTy, aTy[k]);
                aPx[k] = fmaf(w, dPx, aPx[k]);
                aPy[k] = fmaf(w, dPy, aPy[k]);
            }
        }
    }

    // write fp16 cepstra (coalesced half2 per k)
    const int n2 = b * T2 + t2;
#pragma unroll
    for (int k = 0; k < KK; k++) {
        ((__half2*)(g_cT16 + (size_t)k * NN))[n2] = __floats2half2_rn(aTx[k], aTy[k]);
        ((__half2*)(g_cP16 + (size_t)k * NN))[n2] = __floats2half2_rn(aPx[k], aPy[k]);
    }

    // ---- fused stats: per-thread 2 samples -> warp reduce -> shared -> global
    __shared__ float shS[2][KK], shQ[2][KK];
    if (threadIdx.x < 2 * KK) {
        ((float*)shS)[threadIdx.x] = 0.f;
        ((float*)shQ)[threadIdx.x] = 0.f;
    }
    __syncthreads();

    const int lane = threadIdx.x & 31;
#pragma unroll
    for (int k = 0; k < KK; k++) {
        float s0 = aTx[k] + aTy[k];
        float q0 = fmaf(aTx[k], aTx[k], aTy[k] * aTy[k]);
        float s1 = aPx[k] + aPy[k];
        float q1 = fmaf(aPx[k], aPx[k], aPy[k] * aPy[k]);
#pragma unroll
        for (int o = 16; o > 0; o >>= 1) {
            s0 += __shfl_down_sync(0xffffffffu, s0, o);
            q0 += __shfl_down_sync(0xffffffffu, q0, o);
            s1 += __shfl_down_sync(0xffffffffu, s1, o);
            q1 += __shfl_down_sync(0xffffffffu, q1, o);
        }
        if (lane == 0) {
            atomicAdd(&shS[0][k], s0); atomicAdd(&shQ[0][k], q0);
            atomicAdd(&shS[1][k], s1); atomicAdd(&shQ[1][k], q1);
        }
    }
    __syncthreads();
    if (threadIdx.x < 2 * KK) {
        int t = threadIdx.x / KK, k = threadIdx.x % KK;
        atomicAdd(&g_sum[t][k],   (double)shS[t][k]);
        atomicAdd(&g_sumsq[t][k], (double)shQ[t][k]);
    }
}

// ---------------------------------------------------------------------------
// K3: finalize stats (redundant per-block, double), mcd over all (b,t),
// last block writes the final scalar. Grid 512 x 256, 2 samples/thread exact.
// ---------------------------------------------------------------------------
__global__ __launch_bounds__(256) void k3_mcd(float* __restrict__ out) {
    __shared__ float srT[KK], srP[KK], soff[KK];
    if (threadIdx.x < KK) {
        int k = threadIdx.x;
        double sT = g_sum[0][k];
        double mT = sT / (double)NN;
        double vT = (g_sumsq[0][k] - sT * sT / (double)NN) / (double)(NN - 1);
        if (vT < 0.0) vT = 0.0;
        double rT = 1.0 / (sqrt(vT) + 1e-6);
        double sP = g_sum[1][k];
        double mP = sP / (double)NN;
        double vP = (g_sumsq[1][k] - sP * sP / (double)NN) / (double)(NN - 1);
        if (vP < 0.0) vP = 0.0;
        double rP = 1.0 / (sqrt(vP) + 1e-6);
        srT[k]  = (float)rT;
        srP[k]  = (float)rP;
        soff[k] = (float)(mT * rT - mP * rP);
    }
    __syncthreads();

    const int n2 = blockIdx.x * blockDim.x + threadIdx.x;   // 0 .. NN/2-1 exact

    float sx = 0.f, sy = 0.f;
#pragma unroll
    for (int k = 0; k < KK; k++) {
        float2 cT = __half22float2(((const __half2*)(g_cT16 + (size_t)k * NN))[n2]);
        float2 cP = __half22float2(((const __half2*)(g_cP16 + (size_t)k * NN))[n2]);
        float dx = fmaf(cT.x, srT[k], -soff[k]) - cP.x * srP[k];
        float dy = fmaf(cT.y, srT[k], -soff[k]) - cP.y * srP[k];
        sx = fmaf(dx, dx, sx);
        sy = fmaf(dy, dy, sy);
    }
    float acc = sqrtf(2.0f * sx) + sqrtf(2.0f * sy);

    __shared__ float sh_acc;
    if (threadIdx.x == 0) sh_acc = 0.f;
    __syncthreads();
#pragma unroll
    for (int o = 16; o > 0; o >>= 1) acc += __shfl_down_sync(0xffffffffu, acc, o);
    if ((threadIdx.x & 31) == 0) atomicAdd(&sh_acc, acc);
    __syncthreads();

    if (threadIdx.x == 0) {
        atomicAdd(&g_mcd_acc, (double)sh_acc);
        __threadfence();
        unsigned done = atomicAdd(&g_count, 1u);
        if (done == gridDim.x - 1) {
            // read with atomic to guarantee visibility of all prior adds
            double total = atomicAdd(&g_mcd_acc, 0.0);
            out[0] = (float)(total * 4.342944819032518 / (double)NN);  // 10/ln(10), /N
        }
    }
}

extern "C" void kernel_launch(void* const* d_in, const int* in_sizes, int n_in,
                              void* d_out, int out_size) {
    const float* mel_true = (const float*)d_in[0];
    const float* mel_pred = (const float*)d_in[1];
    float* out = (float*)d_out;

    k0_init<<<1, 256>>>();

    dim3 g1(TT / 512, BB);           // 8 x 64 = 512 blocks, 2 t per thread
    k1_dct<<<g1, 256>>>(mel_true, mel_pred);

    k3_mcd<<<512, 256>>>(out);
}

// round 9
// speedup vs baseline: 1.6284x; 1.5549x over previous
#include <cuda_runtime.h>
#include <cuda_fp16.h>
#include <math.h>

// Problem dims (fixed by reference setup_inputs)
#define BB 64
#define FF 128
#define TT 4096
#define KK 13
#define NN (BB*TT)   // 262144 samples per coefficient
#define T2 (TT/2)

// ---- device scratch (static: no allocation allowed; zero-init at load) ----
__device__ __half   g_cT16[(size_t)KK * NN];   // cepstra fp16, layout [k][b*T+t]
__device__ __half   g_cP16[(size_t)KK * NN];
__device__ double   g_sum[2][KK];
__device__ double   g_sumsq[2][KK];
__device__ double   g_mcd_acc;
__device__ unsigned g_count;

// ---------------------------------------------------------------------------
// K1: log2(1+|x|) -> folded 13-pt DCT, fp16 cepstra out, fused stats.
// blockIdx.z selects tensor (0=true, 1=pred) -> 26 accums/thread, high occ.
// Basis built per-block in smem (ln2 and dct scale folded in).
// 4-deep software prefetch of the (f, 127-f) row pairs.
// Grid: (TT/512, BB, 2) x 256; each thread owns 2 adjacent t (float2).
// ---------------------------------------------------------------------------
__global__ __launch_bounds__(256) void k1_dct(const float* __restrict__ xt,
                                              const float* __restrict__ xp) {
    __shared__ float sb[KK][FF/2];
    for (int i = threadIdx.x; i < KK * (FF/2); i += blockDim.x) {
        int k = i >> 6, f = i & 63;
        // sqrt(1/128), sqrt(2/128)=0.125 ; ln2 folded in (we use log2)
        float scale = (k == 0) ? 0.088388347648318447f : 0.125f;
        sb[k][f] = cospif((float)((2*f + 1) * k) * (1.0f/256.0f))
                 * scale * 0.69314718055994531f;
    }
    __syncthreads();

    const int   b   = blockIdx.y;
    const int   z   = blockIdx.z;
    const float* src = z ? xp : xt;
    __half*      dst = z ? g_cP16 : g_cT16;

    const int t2 = blockIdx.x * blockDim.x + threadIdx.x;   // float2 idx along T
    const float2* px = (const float2*)(src + (size_t)b * FF * TT) + t2;

    float ax[KK], ay[KK];
#pragma unroll
    for (int k = 0; k < KK; k++) { ax[k] = 0.f; ay[k] = 0.f; }

    const int PF = 4;
    float2 bl[PF], bh[PF];
#pragma unroll
    for (int j = 0; j < PF; j++) {
        bl[j] = __ldcs(px + (size_t)j * T2);
        bh[j] = __ldcs(px + (size_t)(FF-1-j) * T2);
    }

#pragma unroll 1
    for (int f0 = 0; f0 < FF/2; f0 += PF) {
        float2 cl[PF], ch[PF];
#pragma unroll
        for (int j = 0; j < PF; j++) { cl[j] = bl[j]; ch[j] = bh[j]; }
        if (f0 + PF < FF/2) {
#pragma unroll
            for (int j = 0; j < PF; j++) {
                bl[j] = __ldcs(px + (size_t)(f0 + PF + j) * T2);
                bh[j] = __ldcs(px + (size_t)(FF-1 - (f0 + PF + j)) * T2);
            }
        }
#pragma unroll
        for (int j = 0; j < PF; j++) {
            float llx = __log2f(1.0f + fabsf(cl[j].x));
            float lly = __log2f(1.0f + fabsf(cl[j].y));
            float lhx = __log2f(1.0f + fabsf(ch[j].x));
            float lhy = __log2f(1.0f + fabsf(ch[j].y));
            float sx = llx + lhx, dx = llx - lhx;
            float sy = lly + lhy, dy = lly - lhy;
#pragma unroll
            for (int k = 0; k < KK; k++) {
                float w = sb[k][f0 + j];
                if (k & 1) {
                    ax[k] = fmaf(w, dx, ax[k]);
                    ay[k] = fmaf(w, dy, ay[k]);
                } else {
                    ax[k] = fmaf(w, sx, ax[k]);
                    ay[k] = fmaf(w, sy, ay[k]);
                }
            }
        }
    }

    // write fp16 cepstra (coalesced half2 per k; stays in L2 for K2)
    const int n2 = b * T2 + t2;
#pragma unroll
    for (int k = 0; k < KK; k++)
        ((__half2*)(dst + (size_t)k * NN))[n2] = __floats2half2_rn(ax[k], ay[k]);

    // ---- fused stats: warp reduce -> shared -> one double atomic per k
    __shared__ float shS[KK], shQ[KK];
    if (threadIdx.x < KK) { shS[threadIdx.x] = 0.f; shQ[threadIdx.x] = 0.f; }
    __syncthreads();

    const int lane = threadIdx.x & 31;
#pragma unroll
    for (int k = 0; k < KK; k++) {
        float s = ax[k] + ay[k];
        float q = fmaf(ax[k], ax[k], ay[k] * ay[k]);
#pragma unroll
        for (int o = 16; o > 0; o >>= 1) {
            s += __shfl_down_sync(0xffffffffu, s, o);
            q += __shfl_down_sync(0xffffffffu, q, o);
        }
        if (lane == 0) { atomicAdd(&shS[k], s); atomicAdd(&shQ[k], q); }
    }
    __syncthreads();
    if (threadIdx.x < KK) {
        atomicAdd(&g_sum[z][threadIdx.x],   (double)shS[threadIdx.x]);
        atomicAdd(&g_sumsq[z][threadIdx.x], (double)shQ[threadIdx.x]);
    }
}

// ---------------------------------------------------------------------------
// K2: finalize stats (redundant per-block, double), mcd over all (b,t);
// last block writes the scalar and resets accumulators for the next replay.
// Grid 512 x 256, one half2 (2 samples) per thread, exact cover of NN.
// ---------------------------------------------------------------------------
__global__ __launch_bounds__(256) void k2_mcd(float* __restrict__ out) {
    __shared__ float srT[KK], srP[KK], soff[KK];
    if (threadIdx.x < KK) {
        int k = threadIdx.x;
        double sT = g_sum[0][k];
        double mT = sT / (double)NN;
        double vT = (g_sumsq[0][k] - sT * sT / (double)NN) / (double)(NN - 1);
        if (vT < 0.0) vT = 0.0;
        double rT = 1.0 / (sqrt(vT) + 1e-6);
        double sP = g_sum[1][k];
        double mP = sP / (double)NN;
        double vP = (g_sumsq[1][k] - sP * sP / (double)NN) / (double)(NN - 1);
        if (vP < 0.0) vP = 0.0;
        double rP = 1.0 / (sqrt(vP) + 1e-6);
        srT[k]  = (float)rT;
        srP[k]  = (float)rP;
        soff[k] = (float)(mT * rT - mP * rP);
    }
    __syncthreads();

    const int n2 = blockIdx.x * blockDim.x + threadIdx.x;   // 0 .. NN/2-1

    float sx = 0.f, sy = 0.f;
#pragma unroll
    for (int k = 0; k < KK; k++) {
        float2 cT = __half22float2(((const __half2*)(g_cT16 + (size_t)k * NN))[n2]);
        float2 cP = __half22float2(((const __half2*)(g_cP16 + (size_t)k * NN))[n2]);
        float dx = fmaf(cT.x, srT[k], -soff[k]) - cP.x * srP[k];
        float dy = fmaf(cT.y, srT[k], -soff[k]) - cP.y * srP[k];
        sx = fmaf(dx, dx, sx);
        sy = fmaf(dy, dy, sy);
    }
    float acc = sqrtf(2.0f * sx) + sqrtf(2.0f * sy);

    __shared__ float sh_acc;
    if (threadIdx.x == 0) sh_acc = 0.f;
    __syncthreads();
#pragma unroll
    for (int o = 16; o > 0; o >>= 1) acc += __shfl_down_sync(0xffffffffu, acc, o);
    if ((threadIdx.x & 31) == 0) atomicAdd(&sh_acc, acc);
    __syncthreads();

    if (threadIdx.x == 0) {
        atomicAdd(&g_mcd_acc, (double)sh_acc);
        __threadfence();
        unsigned done = atomicAdd(&g_count, 1u);
        if (done == gridDim.x - 1) {
            double total = atomicAdd(&g_mcd_acc, 0.0);
            out[0] = (float)(total * 4.342944819032518 / (double)NN);  // 10/ln10, /N
            // reset state for the next graph replay (first call uses load-time zeros)
            for (int k = 0; k < KK; k++) {
                g_sum[0][k] = 0.0; g_sum[1][k] = 0.0;
                g_sumsq[0][k] = 0.0; g_sumsq[1][k] = 0.0;
            }
            g_mcd_acc = 0.0;
            __threadfence();
            g_count = 0u;
        }
    }
}

extern "C" void kernel_launch(void* const* d_in, const int* in_sizes, int n_in,
                              void* d_out, int out_size) {
    const float* mel_true = (const float*)d_in[0];
    const float* mel_pred = (const float*)d_in[1];
    float* out = (float*)d_out;

    dim3 g1(TT / 512, BB, 2);        // 8 x 64 x 2 = 1024 blocks, 2 t per thread
    k1_dct<<<g1, 256>>>(mel_true, mel_pred);

    k2_mcd<<<512, 256>>>(out);
}

// round 10
// speedup vs baseline: 1.7652x; 1.0840x over previous
#include <cuda_runtime.h>
#include <cuda_fp16.h>
#include <math.h>

// Problem dims (fixed by reference setup_inputs)
#define BB 64
#define FF 128
#define TT 4096
#define KK 13
#define NN (BB*TT)   // 262144 samples per coefficient
#define T2 (TT/2)

// ---- device scratch (static: no allocation allowed; zero-init at load) ----
__device__ __half   g_cT16[(size_t)KK * NN];   // cepstra fp16, layout [k][b*T+t]
__device__ __half   g_cP16[(size_t)KK * NN];
__device__ double   g_sum[2][KK];
__device__ double   g_sumsq[2][KK];
__device__ double   g_mcd_acc;
__device__ unsigned g_count;

// ---- packed fp32x2 helpers (Blackwell FFMA2 via PTX) ----
__device__ __forceinline__ unsigned long long pack2(float x, float y) {
    unsigned long long r;
    asm("mov.b64 %0, {%1, %2};" : "=l"(r) : "f"(x), "f"(y));
    return r;
}
__device__ __forceinline__ void unpack2(unsigned long long v, float& x, float& y) {
    asm("mov.b64 {%0, %1}, %2;" : "=f"(x), "=f"(y) : "l"(v));
}
__device__ __forceinline__ void fma2(unsigned long long& a,
                                     unsigned long long w,
                                     unsigned long long v) {
    asm("fma.rn.f32x2 %0, %1, %2, %0;" : "+l"(a) : "l"(w), "l"(v));
}

// ---------------------------------------------------------------------------
// K1: log2(1+|x|) -> folded 13-pt DCT (packed f32x2 FMAs), fp16 cepstra out,
// fused per-coefficient stats. blockIdx.z selects tensor (0=true, 1=pred).
// Basis built per-block in smem as duplicated {w,w} pairs (LDS.64 broadcast).
// 4-deep software prefetch of the (f, 127-f) row pairs.
// Grid: (TT/512, BB, 2) x 256; each thread owns 2 adjacent t (float2).
// ---------------------------------------------------------------------------
__global__ __launch_bounds__(256) void k1_dct(const float* __restrict__ xt,
                                              const float* __restrict__ xp) {
    __shared__ float2 sb[KK][FF/2];     // {w, w} duplicated
    for (int i = threadIdx.x; i < KK * (FF/2); i += blockDim.x) {
        int k = i >> 6, f = i & 63;
        // sqrt(1/128), sqrt(2/128)=0.125 ; ln2 folded in (we use log2)
        float scale = (k == 0) ? 0.088388347648318447f : 0.125f;
        float w = cospif((float)((2*f + 1) * k) * (1.0f/256.0f))
                * scale * 0.69314718055994531f;
        sb[k][f] = make_float2(w, w);
    }
    __syncthreads();

    const int   b   = blockIdx.y;
    const int   z   = blockIdx.z;
    const float* src = z ? xp : xt;
    __half*      dst = z ? g_cP16 : g_cT16;

    const int t2 = blockIdx.x * blockDim.x + threadIdx.x;   // float2 idx along T
    const float2* px = (const float2*)(src + (size_t)b * FF * TT) + t2;

    unsigned long long acc[KK];   // packed (ax, ay) fp32 pairs
#pragma unroll
    for (int k = 0; k < KK; k++) acc[k] = 0ull;

    const int PF = 4;
    float2 bl[PF], bh[PF];
#pragma unroll
    for (int j = 0; j < PF; j++) {
        bl[j] = __ldcs(px + (size_t)j * T2);
        bh[j] = __ldcs(px + (size_t)(FF-1-j) * T2);
    }

#pragma unroll 1
    for (int f0 = 0; f0 < FF/2; f0 += PF) {
        float2 cl[PF], ch[PF];
#pragma unroll
        for (int j = 0; j < PF; j++) { cl[j] = bl[j]; ch[j] = bh[j]; }
        if (f0 + PF < FF/2) {
#pragma unroll
            for (int j = 0; j < PF; j++) {
                bl[j] = __ldcs(px + (size_t)(f0 + PF + j) * T2);
                bh[j] = __ldcs(px + (size_t)(FF-1 - (f0 + PF + j)) * T2);
            }
        }
#pragma unroll
        for (int j = 0; j < PF; j++) {
            float llx = __log2f(1.0f + fabsf(cl[j].x));
            float lly = __log2f(1.0f + fabsf(cl[j].y));
            float lhx = __log2f(1.0f + fabsf(ch[j].x));
            float lhy = __log2f(1.0f + fabsf(ch[j].y));
            unsigned long long vs = pack2(llx + lhx, lly + lhy);
            unsigned long long vd = pack2(llx - lhx, lly - lhy);
            const unsigned long long* wrow =
                (const unsigned long long*)&sb[0][f0 + j];
#pragma unroll
            for (int k = 0; k < KK; k++) {
                // sb is [KK][64] float2 -> row stride 64 in ull units
                unsigned long long w = wrow[(size_t)k * (FF/2)];
                fma2(acc[k], w, (k & 1) ? vd : vs);
            }
        }
    }

    // unpack, write fp16 cepstra (coalesced half2 per k; stays in L2 for K2)
    const int n2 = b * T2 + t2;
    float ax[KK], ay[KK];
#pragma unroll
    for (int k = 0; k < KK; k++) {
        unpack2(acc[k], ax[k], ay[k]);
        ((__half2*)(dst + (size_t)k * NN))[n2] = __floats2half2_rn(ax[k], ay[k]);
    }

    // ---- fused stats: warp reduce -> shared -> one double atomic per k
    __shared__ float shS[KK], shQ[KK];
    if (threadIdx.x < KK) { shS[threadIdx.x] = 0.f; shQ[threadIdx.x] = 0.f; }
    __syncthreads();

    const int lane = threadIdx.x & 31;
#pragma unroll
    for (int k = 0; k < KK; k++) {
        float s = ax[k] + ay[k];
        float q = fmaf(ax[k], ax[k], ay[k] * ay[k]);
#pragma unroll
        for (int o = 16; o > 0; o >>= 1) {
            s += __shfl_down_sync(0xffffffffu, s, o);
            q += __shfl_down_sync(0xffffffffu, q, o);
        }
        if (lane == 0) { atomicAdd(&shS[k], s); atomicAdd(&shQ[k], q); }
    }
    __syncthreads();
    if (threadIdx.x < KK) {
        atomicAdd(&g_sum[z][threadIdx.x],   (double)shS[threadIdx.x]);
        atomicAdd(&g_sumsq[z][threadIdx.x], (double)shQ[threadIdx.x]);
    }
}

// ---------------------------------------------------------------------------
// K2: finalize stats (redundant per-block, double), mcd over all (b,t);
// last block writes the scalar and resets accumulators for the next replay.
// Grid 256 x 256; each thread loads uint2 (= 2 half2 = 4 samples) per k.
// ---------------------------------------------------------------------------
__global__ __launch_bounds__(256) void k2_mcd(float* __restrict__ out) {
    __shared__ float srT[KK], srP[KK], soff[KK];
    if (threadIdx.x < KK) {
        int k = threadIdx.x;
        double sT = g_sum[0][k];
        double mT = sT / (double)NN;
        double vT = (g_sumsq[0][k] - sT * sT / (double)NN) / (double)(NN - 1);
        if (vT < 0.0) vT = 0.0;
        double rT = 1.0 / (sqrt(vT) + 1e-6);
        double sP = g_sum[1][k];
        double mP = sP / (double)NN;
        double vP = (g_sumsq[1][k] - sP * sP / (double)NN) / (double)(NN - 1);
        if (vP < 0.0) vP = 0.0;
        double rP = 1.0 / (sqrt(vP) + 1e-6);
        srT[k]  = (float)rT;
        srP[k]  = (float)rP;
        soff[k] = (float)(mT * rT - mP * rP);
    }
    __syncthreads();

    const int n4 = blockIdx.x * blockDim.x + threadIdx.x;   // 0 .. NN/4-1 exact

    float s0 = 0.f, s1 = 0.f, s2 = 0.f, s3 = 0.f;
#pragma unroll
    for (int k = 0; k < KK; k++) {
        uint2 uT = ((const uint2*)(g_cT16 + (size_t)k * NN))[n4];
        uint2 uP = ((const uint2*)(g_cP16 + (size_t)k * NN))[n4];
        float2 cT0 = __half22float2(*(const __half2*)&uT.x);
        float2 cT1 = __half22float2(*(const __half2*)&uT.y);
        float2 cP0 = __half22float2(*(const __half2*)&uP.x);
        float2 cP1 = __half22float2(*(const __half2*)&uP.y);
        float d0 = fmaf(cT0.x, srT[k], -soff[k]) - cP0.x * srP[k];
        float d1 = fmaf(cT0.y, srT[k], -soff[k]) - cP0.y * srP[k];
        float d2 = fmaf(cT1.x, srT[k], -soff[k]) - cP1.x * srP[k];
        float d3 = fmaf(cT1.y, srT[k], -soff[k]) - cP1.y * srP[k];
        s0 = fmaf(d0, d0, s0);
        s1 = fmaf(d1, d1, s1);
        s2 = fmaf(d2, d2, s2);
        s3 = fmaf(d3, d3, s3);
    }
    float acc = sqrtf(2.0f * s0) + sqrtf(2.0f * s1)
              + sqrtf(2.0f * s2) + sqrtf(2.0f * s3);

    __shared__ float sh_acc;
    if (threadIdx.x == 0) sh_acc = 0.f;
    __syncthreads();
#pragma unroll
    for (int o = 16; o > 0; o >>= 1) acc += __shfl_down_sync(0xffffffffu, acc, o);
    if ((threadIdx.x & 31) == 0) atomicAdd(&sh_acc, acc);
    __syncthreads();

    if (threadIdx.x == 0) {
        atomicAdd(&g_mcd_acc, (double)sh_acc);
        __threadfence();
        unsigned done = atomicAdd(&g_count, 1u);
        if (done == gridDim.x - 1) {
            double total = atomicAdd(&g_mcd_acc, 0.0);
            out[0] = (float)(total * 4.342944819032518 / (double)NN);  // 10/ln10, /N
            // reset state for the next graph replay (first call uses load-time zeros)
            for (int k = 0; k < KK; k++) {
                g_sum[0][k] = 0.0; g_sum[1][k] = 0.0;
                g_sumsq[0][k] = 0.0; g_sumsq[1][k] = 0.0;
            }
            g_mcd_acc = 0.0;
            __threadfence();
            g_count = 0u;
        }
    }
}

extern "C" void kernel_launch(void* const* d_in, const int* in_sizes, int n_in,
                              void* d_out, int out_size) {
    const float* mel_true = (const float*)d_in[0];
    const float* mel_pred = (const float*)d_in[1];
    float* out = (float*)d_out;

    dim3 g1(TT / 512, BB, 2);        // 8 x 64 x 2 = 1024 blocks, 2 t per thread
    k1_dct<<<g1, 256>>>(mel_true, mel_pred);

    k2_mcd<<<256, 256>>>(out);       // 4 samples per thread, exact cover
}